// round 3
// baseline (speedup 1.0000x reference)
#include <cuda_runtime.h>
#include <cuda_bf16.h>
#include <cstdint>

// Problem constants
#define Bsz   1024
#define LEN   110
#define DIM   512
#define WP    10
#define WF    10

// GEMM tiling
#define BM 128
#define BN 128
#define BK 16
#define SPAD 4   // smem row pad (132 floats/row)

// Scratch for att = nf @ W^T  (fp32, [B, 110, 512]); rows l >= text_len[b] left untouched.
__device__ float g_att[(size_t)Bsz * LEN * DIM];

// ---------- packed fp32x2 helpers (FFMA2: only reachable via PTX) ----------
__device__ __forceinline__ unsigned long long pack2(float x, float y) {
    unsigned long long r;
    asm("mov.b64 %0, {%1, %2};" : "=l"(r) : "f"(x), "f"(y));
    return r;
}
__device__ __forceinline__ void unpack2(unsigned long long v, float& x, float& y) {
    asm("mov.b64 {%0, %1}, %2;" : "=f"(x), "=f"(y) : "l"(v));
}
__device__ __forceinline__ void ffma2(unsigned long long& d, unsigned long long a, unsigned long long b) {
    asm("fma.rn.f32x2 %0, %1, %2, %3;" : "=l"(d) : "l"(a), "l"(b), "l"(d));
}

// ============================================================================
// Kernel 1: att[b,l,d] = sum_e nf[b,l,e] * W[d,e]
// Per-batch M-tile (128 rows covering l=0..109, padded), BN=128 over d, BK=16.
// Software-pipelined k-loop (register prefetch of next tile, 2x float4 each).
// Warp-level skip of row-groups with l >= text_len[b]; stores also skipped.
// ============================================================================
__global__ __launch_bounds__(256, 2)
void edgeatt_gemm(const float* __restrict__ nf,
                  const float* __restrict__ W,
                  const int*   __restrict__ text_len,
                  float*       __restrict__ att)
{
    __shared__ float As[BK][BM + SPAD];
    __shared__ float Bs[BK][BN + SPAD];

    const int t    = threadIdx.x;            // 0..255
    const int b    = blockIdx.y;             // batch
    const int nblk = blockIdx.x * BN;        // d offset (0,128,256,384)
    const int len  = text_len[b];            // 1..110

    const int tx = t & 15;                   // col group (8 cols each)
    const int ty = t >> 4;                   // row group (8 rows each)
    const int warp_row0 = (t >> 5) << 4;     // first row this warp touches (16-row granularity)
    const bool act = (warp_row0 < len);      // warp-uniform compute-skip

    // cooperative load mapping: 128 rows x 16 cols, two float4 per thread
    const int lrow = t >> 1;                 // 0..127
    const int lcol = (t & 1) * 8;            // 0 or 8  (covers lcol..lcol+7)

    const float* Arow = nf + ((size_t)b * LEN + lrow) * DIM + lcol;   // valid iff lrow < len
    const float* Wrow = W + ((size_t)(nblk + lrow)) * DIM + lcol;     // always valid
    const bool a_valid = (lrow < len);

    unsigned long long acc[8][4];
    #pragma unroll
    for (int i = 0; i < 8; i++)
        #pragma unroll
        for (int j = 0; j < 4; j++) acc[i][j] = 0ull;

    // ---- prologue: prefetch k=0 tile into registers ----
    float4 av0 = make_float4(0.f, 0.f, 0.f, 0.f), av1 = av0;
    if (a_valid) {
        av0 = *reinterpret_cast<const float4*>(Arow);
        av1 = *reinterpret_cast<const float4*>(Arow + 4);
    }
    float4 wv0 = *reinterpret_cast<const float4*>(Wrow);
    float4 wv1 = *reinterpret_cast<const float4*>(Wrow + 4);

    for (int k = 0; k < DIM; k += BK) {
        __syncthreads();    // previous compute done reading smem
        As[lcol + 0][lrow] = av0.x; As[lcol + 1][lrow] = av0.y;
        As[lcol + 2][lrow] = av0.z; As[lcol + 3][lrow] = av0.w;
        As[lcol + 4][lrow] = av1.x; As[lcol + 5][lrow] = av1.y;
        As[lcol + 6][lrow] = av1.z; As[lcol + 7][lrow] = av1.w;
        Bs[lcol + 0][lrow] = wv0.x; Bs[lcol + 1][lrow] = wv0.y;
        Bs[lcol + 2][lrow] = wv0.z; Bs[lcol + 3][lrow] = wv0.w;
        Bs[lcol + 4][lrow] = wv1.x; Bs[lcol + 5][lrow] = wv1.y;
        Bs[lcol + 6][lrow] = wv1.z; Bs[lcol + 7][lrow] = wv1.w;
        __syncthreads();

        // prefetch next tile while computing this one
        if (k + BK < DIM) {
            if (a_valid) {
                av0 = *reinterpret_cast<const float4*>(Arow + k + BK);
                av1 = *reinterpret_cast<const float4*>(Arow + k + BK + 4);
            }
            wv0 = *reinterpret_cast<const float4*>(Wrow + k + BK);
            wv1 = *reinterpret_cast<const float4*>(Wrow + k + BK + 4);
        }

        if (act) {
            #pragma unroll
            for (int e = 0; e < BK; e++) {
                float4 a0 = *reinterpret_cast<const float4*>(&As[e][ty * 8]);
                float4 a1 = *reinterpret_cast<const float4*>(&As[e][ty * 8 + 4]);
                float4 b0 = *reinterpret_cast<const float4*>(&Bs[e][tx * 8]);
                float4 b1 = *reinterpret_cast<const float4*>(&Bs[e][tx * 8 + 4]);

                unsigned long long bp[4];
                bp[0] = pack2(b0.x, b0.y); bp[1] = pack2(b0.z, b0.w);
                bp[2] = pack2(b1.x, b1.y); bp[3] = pack2(b1.z, b1.w);

                float afr[8] = {a0.x, a0.y, a0.z, a0.w, a1.x, a1.y, a1.z, a1.w};
                #pragma unroll
                for (int i = 0; i < 8; i++) {
                    unsigned long long ap = pack2(afr[i], afr[i]);
                    #pragma unroll
                    for (int j = 0; j < 4; j++) ffma2(acc[i][j], ap, bp[j]);
                }
            }
        }
    }

    // epilogue: store rows < len only (rows >= len never read downstream)
    #pragma unroll
    for (int i = 0; i < 8; i++) {
        const int row = ty * 8 + i;
        if (row < len) {
            float4 o0, o1;
            unpack2(acc[i][0], o0.x, o0.y); unpack2(acc[i][1], o0.z, o0.w);
            unpack2(acc[i][2], o1.x, o1.y); unpack2(acc[i][3], o1.z, o1.w);
            float* crow = att + ((size_t)b * LEN + row) * DIM + nblk + tx * 8;
            *reinterpret_cast<float4*>(crow)     = o0;
            *reinterpret_cast<float4*>(crow + 4) = o1;
        }
    }
}

// ============================================================================
// Kernel 2: windowed scores + softmax + scatter.
// One block (128 threads, 4 warps) per (b, j).
//   scores[l] = dot(att[b,l,:], nf[b,j,:])  for l in [max(0,j-10), min(j+10,len-1)]
//   probs = softmax(scores) over window; out row zero elsewhere.
// ============================================================================
__global__ __launch_bounds__(128)
void edgeatt_softmax(const float* __restrict__ nf,
                     const float* __restrict__ att,
                     const int*   __restrict__ text_len,
                     float*       __restrict__ out)
{
    const int j = blockIdx.x;      // 0..109
    const int b = blockIdx.y;      // 0..1023
    const int t = threadIdx.x;     // 0..127
    const int len = text_len[b];

    float* orow = out + ((size_t)b * LEN + j) * LEN;

    if (j >= len) {
        for (int i = t; i < LEN; i += 128) orow[i] = 0.f;
        return;
    }

    const int lo  = (j - WP > 0) ? (j - WP) : 0;
    const int hi  = (j + WF < len - 1) ? (j + WF) : (len - 1);
    const int cnt = hi - lo + 1;     // 1..21

    const int lane = t & 31;
    const int w    = t >> 5;

    // q = nf[b,j,:] in registers (16 floats/lane, coalesced float4 loads)
    const float4* q4 = reinterpret_cast<const float4*>(nf + ((size_t)b * LEN + j) * DIM);
    float4 q[4];
    #pragma unroll
    for (int i = 0; i < 4; i++) q[i] = q4[i * 32 + lane];

    __shared__ float s_scores[24];
    __shared__ float s_probs[24];

    for (int li = w; li < cnt; li += 4) {
        const int l = lo + li;
        const float4* a4 = reinterpret_cast<const float4*>(att + ((size_t)b * LEN + l) * DIM);
        float s0, s1, s2, s3;
        {
            float4 av0 = a4[0 * 32 + lane];
            float4 av1 = a4[1 * 32 + lane];
            float4 av2 = a4[2 * 32 + lane];
            float4 av3 = a4[3 * 32 + lane];
            s0 = fmaf(av0.x, q[0].x, fmaf(av0.y, q[0].y, fmaf(av0.z, q[0].z, av0.w * q[0].w)));
            s1 = fmaf(av1.x, q[1].x, fmaf(av1.y, q[1].y, fmaf(av1.z, q[1].z, av1.w * q[1].w)));
            s2 = fmaf(av2.x, q[2].x, fmaf(av2.y, q[2].y, fmaf(av2.z, q[2].z, av2.w * q[2].w)));
            s3 = fmaf(av3.x, q[3].x, fmaf(av3.y, q[3].y, fmaf(av3.z, q[3].z, av3.w * q[3].w)));
        }
        float s = (s0 + s1) + (s2 + s3);
        #pragma unroll
        for (int off = 16; off; off >>= 1)
            s += __shfl_xor_sync(0xffffffffu, s, off);
        if (lane == 0) s_scores[li] = s;
    }
    __syncthreads();

    if (t < 32) {
        float v = (t < cnt) ? s_scores[t] : -3.0e38f;
        float m = v;
        #pragma unroll
        for (int off = 16; off; off >>= 1)
            m = fmaxf(m, __shfl_xor_sync(0xffffffffu, m, off));
        float e = (t < cnt) ? __expf(v - m) : 0.f;
        float sum = e;
        #pragma unroll
        for (int off = 16; off; off >>= 1)
            sum += __shfl_xor_sync(0xffffffffu, sum, off);
        if (t < cnt) s_probs[t] = e / sum;
    }
    __syncthreads();

    // 110 outputs per row: window probs, zeros elsewhere
    #pragma unroll
    for (int i = t; i < LEN; i += 128) {
        float val = (i >= lo && i <= hi) ? s_probs[i - lo] : 0.f;
        orow[i] = val;
    }
}

// ============================================================================
extern "C" void kernel_launch(void* const* d_in, const int* in_sizes, int n_in,
                              void* d_out, int out_size)
{
    const float* nf       = (const float*)d_in[0];   // [1024,110,512] f32
    const float* W        = (const float*)d_in[1];   // [512,512] f32
    const int*   text_len = (const int*)d_in[2];     // [1024] i32
    float*       out      = (float*)d_out;           // [1024,110,110] f32

    (void)in_sizes; (void)n_in; (void)out_size;

    dim3 g1(DIM / BN, Bsz);          // (4, 1024)
    edgeatt_gemm<<<g1, 256>>>(nf, W, text_len, g_att);

    dim3 g2(LEN, Bsz);               // (110, 1024)
    edgeatt_softmax<<<g2, 128>>>(nf, g_att, text_len, out);
}

// round 4
// speedup vs baseline: 1.0005x; 1.0005x over previous
#include <cuda_runtime.h>
#include <cuda_bf16.h>
#include <cstdint>

// Problem constants
#define Bsz   1024
#define LEN   110
#define DIM   512
#define WP    10
#define WF    10

// GEMM tiling
#define BM 128
#define BN 128
#define BK 16
#define SPAD 4   // smem row pad (132 floats/row)

// Scratch for att = nf @ W^T  (fp32, [B, 110, 512]); rows l >= text_len[b] left untouched.
__device__ float g_att[(size_t)Bsz * LEN * DIM];

// ============================================================================
// Kernel 1: att[b,l,d] = sum_e nf[b,l,e] * W[d,e]
// Per-batch M-tile (128 rows covering l=0..109, padded), BN=128 over d, BK=16.
// Plain fp32 register-tiled SGEMM: 8x8 per thread, float accumulators.
// Register prefetch of next k-tile; warp-granular skip of rows >= text_len[b].
// ============================================================================
__global__ __launch_bounds__(256, 2)
void edgeatt_gemm(const float* __restrict__ nf,
                  const float* __restrict__ W,
                  const int*   __restrict__ text_len,
                  float*       __restrict__ att)
{
    __shared__ float As[BK][BM + SPAD];
    __shared__ float Bs[BK][BN + SPAD];

    const int t    = threadIdx.x;            // 0..255
    const int b    = blockIdx.y;             // batch
    const int nblk = blockIdx.x * BN;        // d offset (0,128,256,384)
    const int len  = text_len[b];            // 1..110

    const int tx = t & 15;                   // col group (8 cols each)
    const int ty = t >> 4;                   // row group (8 rows each)
    const int warp_row0 = (t >> 5) << 4;     // first row this warp touches (16-row granularity)
    const bool act = (warp_row0 < len);      // warp-uniform compute-skip

    // cooperative load mapping: 128 rows x 16 cols, two float4 per thread
    const int lrow = t >> 1;                 // 0..127
    const int lcol = (t & 1) * 8;            // 0 or 8  (covers lcol..lcol+7)

    const float* Arow = nf + ((size_t)b * LEN + lrow) * DIM + lcol;   // valid iff lrow < len
    const float* Wrow = W + ((size_t)(nblk + lrow)) * DIM + lcol;     // always valid
    const bool a_valid = (lrow < len);

    float acc[8][8];
    #pragma unroll
    for (int i = 0; i < 8; i++)
        #pragma unroll
        for (int j = 0; j < 8; j++) acc[i][j] = 0.f;

    // ---- prologue: prefetch k=0 tile into registers ----
    float4 av0 = make_float4(0.f, 0.f, 0.f, 0.f), av1 = av0;
    if (a_valid) {
        av0 = *reinterpret_cast<const float4*>(Arow);
        av1 = *reinterpret_cast<const float4*>(Arow + 4);
    }
    float4 wv0 = *reinterpret_cast<const float4*>(Wrow);
    float4 wv1 = *reinterpret_cast<const float4*>(Wrow + 4);

    for (int k = 0; k < DIM; k += BK) {
        __syncthreads();    // previous compute done reading smem
        As[lcol + 0][lrow] = av0.x; As[lcol + 1][lrow] = av0.y;
        As[lcol + 2][lrow] = av0.z; As[lcol + 3][lrow] = av0.w;
        As[lcol + 4][lrow] = av1.x; As[lcol + 5][lrow] = av1.y;
        As[lcol + 6][lrow] = av1.z; As[lcol + 7][lrow] = av1.w;
        Bs[lcol + 0][lrow] = wv0.x; Bs[lcol + 1][lrow] = wv0.y;
        Bs[lcol + 2][lrow] = wv0.z; Bs[lcol + 3][lrow] = wv0.w;
        Bs[lcol + 4][lrow] = wv1.x; Bs[lcol + 5][lrow] = wv1.y;
        Bs[lcol + 6][lrow] = wv1.z; Bs[lcol + 7][lrow] = wv1.w;
        __syncthreads();

        // prefetch next tile while computing this one
        if (k + BK < DIM) {
            if (a_valid) {
                av0 = *reinterpret_cast<const float4*>(Arow + k + BK);
                av1 = *reinterpret_cast<const float4*>(Arow + k + BK + 4);
            }
            wv0 = *reinterpret_cast<const float4*>(Wrow + k + BK);
            wv1 = *reinterpret_cast<const float4*>(Wrow + k + BK + 4);
        }

        if (act) {
            #pragma unroll
            for (int e = 0; e < BK; e++) {
                float4 a0 = *reinterpret_cast<const float4*>(&As[e][ty * 8]);
                float4 a1 = *reinterpret_cast<const float4*>(&As[e][ty * 8 + 4]);
                float4 b0 = *reinterpret_cast<const float4*>(&Bs[e][tx * 8]);
                float4 b1 = *reinterpret_cast<const float4*>(&Bs[e][tx * 8 + 4]);

                const float af[8] = {a0.x, a0.y, a0.z, a0.w, a1.x, a1.y, a1.z, a1.w};
                const float bf[8] = {b0.x, b0.y, b0.z, b0.w, b1.x, b1.y, b1.z, b1.w};

                #pragma unroll
                for (int i = 0; i < 8; i++)
                    #pragma unroll
                    for (int j = 0; j < 8; j++)
                        acc[i][j] = fmaf(af[i], bf[j], acc[i][j]);
            }
        }
    }

    // epilogue: store rows < len only (rows >= len never read downstream)
    #pragma unroll
    for (int i = 0; i < 8; i++) {
        const int row = ty * 8 + i;
        if (row < len) {
            float4 o0, o1;
            o0.x = acc[i][0]; o0.y = acc[i][1]; o0.z = acc[i][2]; o0.w = acc[i][3];
            o1.x = acc[i][4]; o1.y = acc[i][5]; o1.z = acc[i][6]; o1.w = acc[i][7];
            float* crow = att + ((size_t)b * LEN + row) * DIM + nblk + tx * 8;
            *reinterpret_cast<float4*>(crow)     = o0;
            *reinterpret_cast<float4*>(crow + 4) = o1;
        }
    }
}

// ============================================================================
// Kernel 2: windowed scores + softmax + scatter.
// One block (128 threads, 4 warps) per (b, j).
//   scores[l] = dot(att[b,l,:], nf[b,j,:])  for l in [max(0,j-10), min(j+10,len-1)]
//   probs = softmax(scores) over window; out row zero elsewhere.
// ============================================================================
__global__ __launch_bounds__(128)
void edgeatt_softmax(const float* __restrict__ nf,
                     const float* __restrict__ att,
                     const int*   __restrict__ text_len,
                     float*       __restrict__ out)
{
    const int j = blockIdx.x;      // 0..109
    const int b = blockIdx.y;      // 0..1023
    const int t = threadIdx.x;     // 0..127
    const int len = text_len[b];

    float* orow = out + ((size_t)b * LEN + j) * LEN;

    if (j >= len) {
        for (int i = t; i < LEN; i += 128) orow[i] = 0.f;
        return;
    }

    const int lo  = (j - WP > 0) ? (j - WP) : 0;
    const int hi  = (j + WF < len - 1) ? (j + WF) : (len - 1);
    const int cnt = hi - lo + 1;     // 1..21

    const int lane = t & 31;
    const int w    = t >> 5;

    // q = nf[b,j,:] in registers (16 floats/lane, coalesced float4 loads)
    const float4* q4 = reinterpret_cast<const float4*>(nf + ((size_t)b * LEN + j) * DIM);
    float4 q[4];
    #pragma unroll
    for (int i = 0; i < 4; i++) q[i] = q4[i * 32 + lane];

    __shared__ float s_scores[24];
    __shared__ float s_probs[24];

    for (int li = w; li < cnt; li += 4) {
        const int l = lo + li;
        const float4* a4 = reinterpret_cast<const float4*>(att + ((size_t)b * LEN + l) * DIM);
        float s0, s1, s2, s3;
        {
            float4 av0 = a4[0 * 32 + lane];
            float4 av1 = a4[1 * 32 + lane];
            float4 av2 = a4[2 * 32 + lane];
            float4 av3 = a4[3 * 32 + lane];
            s0 = fmaf(av0.x, q[0].x, fmaf(av0.y, q[0].y, fmaf(av0.z, q[0].z, av0.w * q[0].w)));
            s1 = fmaf(av1.x, q[1].x, fmaf(av1.y, q[1].y, fmaf(av1.z, q[1].z, av1.w * q[1].w)));
            s2 = fmaf(av2.x, q[2].x, fmaf(av2.y, q[2].y, fmaf(av2.z, q[2].z, av2.w * q[2].w)));
            s3 = fmaf(av3.x, q[3].x, fmaf(av3.y, q[3].y, fmaf(av3.z, q[3].z, av3.w * q[3].w)));
        }
        float s = (s0 + s1) + (s2 + s3);
        #pragma unroll
        for (int off = 16; off; off >>= 1)
            s += __shfl_xor_sync(0xffffffffu, s, off);
        if (lane == 0) s_scores[li] = s;
    }
    __syncthreads();

    if (t < 32) {
        float v = (t < cnt) ? s_scores[t] : -3.0e38f;
        float m = v;
        #pragma unroll
        for (int off = 16; off; off >>= 1)
            m = fmaxf(m, __shfl_xor_sync(0xffffffffu, m, off));
        float e = (t < cnt) ? __expf(v - m) : 0.f;
        float sum = e;
        #pragma unroll
        for (int off = 16; off; off >>= 1)
            sum += __shfl_xor_sync(0xffffffffu, sum, off);
        if (t < cnt) s_probs[t] = e / sum;
    }
    __syncthreads();

    // 110 outputs per row: window probs, zeros elsewhere
    #pragma unroll
    for (int i = t; i < LEN; i += 128) {
        float val = (i >= lo && i <= hi) ? s_probs[i - lo] : 0.f;
        orow[i] = val;
    }
}

// ============================================================================
extern "C" void kernel_launch(void* const* d_in, const int* in_sizes, int n_in,
                              void* d_out, int out_size)
{
    const float* nf       = (const float*)d_in[0];   // [1024,110,512] f32
    const float* W        = (const float*)d_in[1];   // [512,512] f32
    const int*   text_len = (const int*)d_in[2];     // [1024] i32
    float*       out      = (float*)d_out;           // [1024,110,110] f32

    (void)in_sizes; (void)n_in; (void)out_size;

    dim3 g1(DIM / BN, Bsz);          // (4, 1024)
    edgeatt_gemm<<<g1, 256>>>(nf, W, text_len, g_att);

    dim3 g2(LEN, Bsz);               // (110, 1024)
    edgeatt_softmax<<<g2, 128>>>(nf, g_att, text_len, out);
}

// round 12
// speedup vs baseline: 1.0267x; 1.0262x over previous
#include <cuda_runtime.h>
#include <cuda_bf16.h>
#include <cstdint>

// Problem constants
#define Bsz   1024
#define LEN   110
#define DIM   512
#define WP    10
#define WF    10

// GEMM tiling: 128x64 block tile, 8x4 per thread (32 accs -> ~90 regs, NO spill
// risk even under the 128-reg cap of __launch_bounds__(256,2); 2 CTAs/SM).
#define BM 128
#define BN 64
#define BK 16
#define SPAD 4

// Scratch for att = nf @ W^T  (fp32, [B, 110, 512]); rows l >= text_len[b] left untouched.
__device__ float g_att[(size_t)Bsz * LEN * DIM];

// no-op kernel: padding launches so ncu's "-s 5 -c 1" lands on edgeatt_gemm
__global__ void nop_kernel() {}

// ============================================================================
// Kernel 1: att[b,l,d] = sum_e nf[b,l,e] * W[d,e]
// grid (DIM/BN=8, Bsz), block 256. Register prefetch of next k-tile.
// Warp-granular skip of row-groups with l >= text_len[b]; stores also skipped.
// ============================================================================
__global__ __launch_bounds__(256, 2)
void edgeatt_gemm(const float* __restrict__ nf,
                  const float* __restrict__ W,
                  const int*   __restrict__ text_len,
                  float*       __restrict__ att)
{
    __shared__ float As[BK][BM + SPAD];
    __shared__ float Bs[BK][BN + SPAD];

    const int t    = threadIdx.x;            // 0..255
    const int b    = blockIdx.y;             // batch
    const int nblk = blockIdx.x * BN;        // d offset (0,64,...,448)
    const int len  = text_len[b];            // 1..110

    const int tx = t & 15;                   // col group (4 cols each) -> 64 cols
    const int ty = t >> 4;                   // row group (8 rows each) -> 128 rows
    const int warp_row0 = (t >> 5) << 4;     // first row this warp touches (16-row granularity)
    const bool act = (warp_row0 < len);      // warp-uniform compute-skip

    // cooperative load mapping
    // A: 128 rows x 16 cols = 512 float4 -> 2 float4/thread
    const int arow = t >> 1;                 // 0..127
    const int acol = (t & 1) * 8;            // 0 or 8 (covers acol..acol+7)
    // B: 64 rows x 16 cols = 256 float4 -> 1 float4/thread
    const int brow = t >> 2;                 // 0..63
    const int bcol = (t & 3) * 4;            // 0,4,8,12

    const float* Arow = nf + ((size_t)b * LEN + arow) * DIM + acol;   // valid iff arow < len
    const float* Wrow = W + ((size_t)(nblk + brow)) * DIM + bcol;     // always valid
    const bool a_valid = (arow < len);

    float acc[8][4];
    #pragma unroll
    for (int i = 0; i < 8; i++)
        #pragma unroll
        for (int j = 0; j < 4; j++) acc[i][j] = 0.f;

    // ---- prologue: prefetch k=0 tile into registers ----
    float4 av0 = make_float4(0.f, 0.f, 0.f, 0.f), av1 = av0;
    if (a_valid) {
        av0 = *reinterpret_cast<const float4*>(Arow);
        av1 = *reinterpret_cast<const float4*>(Arow + 4);
    }
    float4 wv = *reinterpret_cast<const float4*>(Wrow);

    for (int k = 0; k < DIM; k += BK) {
        __syncthreads();    // previous compute done reading smem
        As[acol + 0][arow] = av0.x; As[acol + 1][arow] = av0.y;
        As[acol + 2][arow] = av0.z; As[acol + 3][arow] = av0.w;
        As[acol + 4][arow] = av1.x; As[acol + 5][arow] = av1.y;
        As[acol + 6][arow] = av1.z; As[acol + 7][arow] = av1.w;
        Bs[bcol + 0][brow] = wv.x;  Bs[bcol + 1][brow] = wv.y;
        Bs[bcol + 2][brow] = wv.z;  Bs[bcol + 3][brow] = wv.w;
        __syncthreads();

        // prefetch next tile while computing this one
        if (k + BK < DIM) {
            if (a_valid) {
                av0 = *reinterpret_cast<const float4*>(Arow + k + BK);
                av1 = *reinterpret_cast<const float4*>(Arow + k + BK + 4);
            }
            wv = *reinterpret_cast<const float4*>(Wrow + k + BK);
        }

        if (act) {
            #pragma unroll
            for (int e = 0; e < BK; e++) {
                float4 a0 = *reinterpret_cast<const float4*>(&As[e][ty * 8]);
                float4 a1 = *reinterpret_cast<const float4*>(&As[e][ty * 8 + 4]);
                float4 b0 = *reinterpret_cast<const float4*>(&Bs[e][tx * 4]);

                const float af[8] = {a0.x, a0.y, a0.z, a0.w, a1.x, a1.y, a1.z, a1.w};
                const float bf[4] = {b0.x, b0.y, b0.z, b0.w};

                #pragma unroll
                for (int i = 0; i < 8; i++)
                    #pragma unroll
                    for (int j = 0; j < 4; j++)
                        acc[i][j] = fmaf(af[i], bf[j], acc[i][j]);
            }
        }
    }

    // epilogue: store rows < len only (rows >= len never read downstream)
    #pragma unroll
    for (int i = 0; i < 8; i++) {
        const int row = ty * 8 + i;
        if (row < len) {
            float4 o;
            o.x = acc[i][0]; o.y = acc[i][1]; o.z = acc[i][2]; o.w = acc[i][3];
            float* crow = att + ((size_t)b * LEN + row) * DIM + nblk + tx * 4;
            *reinterpret_cast<float4*>(crow) = o;
        }
    }
}

// ============================================================================
// Kernel 2: windowed scores + softmax + scatter. (UNCHANGED from R4 measurement)
// ============================================================================
__global__ __launch_bounds__(128)
void edgeatt_softmax(const float* __restrict__ nf,
                     const float* __restrict__ att,
                     const int*   __restrict__ text_len,
                     float*       __restrict__ out)
{
    const int j = blockIdx.x;      // 0..109
    const int b = blockIdx.y;      // 0..1023
    const int t = threadIdx.x;     // 0..127
    const int len = text_len[b];

    float* orow = out + ((size_t)b * LEN + j) * LEN;

    if (j >= len) {
        for (int i = t; i < LEN; i += 128) orow[i] = 0.f;
        return;
    }

    const int lo  = (j - WP > 0) ? (j - WP) : 0;
    const int hi  = (j + WF < len - 1) ? (j + WF) : (len - 1);
    const int cnt = hi - lo + 1;     // 1..21

    const int lane = t & 31;
    const int w    = t >> 5;

    const float4* q4 = reinterpret_cast<const float4*>(nf + ((size_t)b * LEN + j) * DIM);
    float4 q[4];
    #pragma unroll
    for (int i = 0; i < 4; i++) q[i] = q4[i * 32 + lane];

    __shared__ float s_scores[24];
    __shared__ float s_probs[24];

    for (int li = w; li < cnt; li += 4) {
        const int l = lo + li;
        const float4* a4 = reinterpret_cast<const float4*>(att + ((size_t)b * LEN + l) * DIM);
        float s0, s1, s2, s3;
        {
            float4 av0 = a4[0 * 32 + lane];
            float4 av1 = a4[1 * 32 + lane];
            float4 av2 = a4[2 * 32 + lane];
            float4 av3 = a4[3 * 32 + lane];
            s0 = fmaf(av0.x, q[0].x, fmaf(av0.y, q[0].y, fmaf(av0.z, q[0].z, av0.w * q[0].w)));
            s1 = fmaf(av1.x, q[1].x, fmaf(av1.y, q[1].y, fmaf(av1.z, q[1].z, av1.w * q[1].w)));
            s2 = fmaf(av2.x, q[2].x, fmaf(av2.y, q[2].y, fmaf(av2.z, q[2].z, av2.w * q[2].w)));
            s3 = fmaf(av3.x, q[3].x, fmaf(av3.y, q[3].y, fmaf(av3.z, q[3].z, av3.w * q[3].w)));
        }
        float s = (s0 + s1) + (s2 + s3);
        #pragma unroll
        for (int off = 16; off; off >>= 1)
            s += __shfl_xor_sync(0xffffffffu, s, off);
        if (lane == 0) s_scores[li] = s;
    }
    __syncthreads();

    if (t < 32) {
        float v = (t < cnt) ? s_scores[t] : -3.0e38f;
        float m = v;
        #pragma unroll
        for (int off = 16; off; off >>= 1)
            m = fmaxf(m, __shfl_xor_sync(0xffffffffu, m, off));
        float e = (t < cnt) ? __expf(v - m) : 0.f;
        float sum = e;
        #pragma unroll
        for (int off = 16; off; off >>= 1)
            sum += __shfl_xor_sync(0xffffffffu, sum, off);
        if (t < cnt) s_probs[t] = e / sum;
    }
    __syncthreads();

    #pragma unroll
    for (int i = t; i < LEN; i += 128) {
        float val = (i >= lo && i <= hi) ? s_probs[i - lo] : 0.f;
        orow[i] = val;
    }
}

// ============================================================================
extern "C" void kernel_launch(void* const* d_in, const int* in_sizes, int n_in,
                              void* d_out, int out_size)
{
    const float* nf       = (const float*)d_in[0];   // [1024,110,512] f32
    const float* W        = (const float*)d_in[1];   // [512,512] f32
    const int*   text_len = (const int*)d_in[2];     // [1024] i32
    float*       out      = (float*)d_out;           // [1024,110,110] f32

    (void)in_sizes; (void)n_in; (void)out_size;

    dim3 g1(DIM / BN, Bsz);          // (8, 1024)
    edgeatt_gemm<<<g1, 256>>>(nf, W, text_len, g_att);

    dim3 g2(LEN, Bsz);               // (110, 1024)
    edgeatt_softmax<<<g2, 128>>>(nf, g_att, text_len, out);

    // 3 no-op launches -> 5 launches per call; ncu "-s 5 -c 1" then captures
    // the SECOND call's edgeatt_gemm instead of always hitting the softmax.
    nop_kernel<<<1, 32>>>();
    nop_kernel<<<1, 32>>>();
    nop_kernel<<<1, 32>>>();
}